// round 16
// baseline (speedup 1.0000x reference)
#include <cuda_runtime.h>
#include <cuda_fp16.h>
#include <cstdint>

typedef unsigned long long u64;

// Problem constants
#define NN  128      // N (msa rows)
#define LL  256      // L (sequence)
#define DD  256      // D (model dim)
#define PP  128      // P (pair channels)
#define HH  8        // heads
#define DH  32       // head dim

#define QSCALE 0.17677669529663687f   // 32^-0.5
#define LOG2E  1.4426950408889634f

// Scratch (device globals — no allocation allowed)
__device__ float   g_bias[(size_t)HH * LL * LL];      // [h][q][k] : (pb-2)*log2e
__device__ __half  g_qkvb_hi[(size_t)NN * LL * 768];  // [n][l][768] (q pre-scaled by QSCALE*LOG2E)
__device__ __half  g_qkvb_lo[(size_t)NN * LL * 768];  // lo split (k cols only)
__device__ __half  g_msa_h[(size_t)NN * LL * DD];     // msa fp16
__device__ __half  g_att_h[(size_t)NN * LL * DD];     // attn out fp16
__device__ __half  g_wqkv_t[768 * 256];               // [n][k] fp16
__device__ __half  g_wout_t[256 * 256];
__device__ int     g_mask_is_byte;

// ===========================================================================
// Helpers
// ===========================================================================
__device__ __forceinline__ uint32_t smem_u32(const void* p) {
    uint32_t a;
    asm("{ .reg .u64 t; cvta.to.shared.u64 t, %1; cvt.u32.u64 %0, t; }" : "=r"(a) : "l"(p));
    return a;
}
__device__ __forceinline__ void ldsm_x4(uint32_t* r, uint32_t addr) {
    asm volatile("ldmatrix.sync.aligned.m8n8.x4.shared.b16 {%0,%1,%2,%3}, [%4];"
                 : "=r"(r[0]), "=r"(r[1]), "=r"(r[2]), "=r"(r[3]) : "r"(addr));
}
__device__ __forceinline__ void ldsm_x4t(uint32_t* r, uint32_t addr) {
    asm volatile("ldmatrix.sync.aligned.m8n8.x4.trans.shared.b16 {%0,%1,%2,%3}, [%4];"
                 : "=r"(r[0]), "=r"(r[1]), "=r"(r[2]), "=r"(r[3]) : "r"(addr));
}
__device__ __forceinline__ void mma_f16(float* d, const uint32_t* a, const uint32_t* b) {
    asm volatile("mma.sync.aligned.m16n8k16.row.col.f32.f16.f16.f32 "
                 "{%0,%1,%2,%3}, {%4,%5,%6,%7}, {%8,%9}, {%0,%1,%2,%3};"
                 : "+f"(d[0]), "+f"(d[1]), "+f"(d[2]), "+f"(d[3])
                 : "r"(a[0]), "r"(a[1]), "r"(a[2]), "r"(a[3]), "r"(b[0]), "r"(b[1]));
}
__device__ __forceinline__ uint32_t pack_h2(__half x, __half y) {
    __half2 t = __halves2half2(x, y);
    return *(uint32_t*)&t;
}
__device__ __forceinline__ uint32_t cvt_h2(float x, float y) {
    uint32_t d;
    asm("cvt.rn.f16x2.f32 %0, %1, %2;" : "=r"(d) : "f"(y), "f"(x));
    return d;
}
__device__ __forceinline__ uint32_t ex2_h2(uint32_t a) {
    uint32_t d;
    asm("ex2.approx.f16x2 %0, %1;" : "=r"(d) : "r"(a));
    return d;
}
__device__ __forceinline__ uint32_t mul_h2(uint32_t a, uint32_t b) {
    uint32_t d;
    asm("mul.rn.f16x2 %0, %1, %2;" : "=r"(d) : "r"(a), "r"(b));
    return d;
}
__device__ __forceinline__ void cp16(uint32_t dst, const void* src) {
    asm volatile("cp.async.cg.shared.global [%0], [%1], 16;" :: "r"(dst), "l"(src) : "memory");
}
#define CP_COMMIT() asm volatile("cp.async.commit_group;" ::: "memory")
#define CP_WAIT0()  asm volatile("cp.async.wait_group 0;" ::: "memory")
#define CP_WAIT1()  asm volatile("cp.async.wait_group 1;" ::: "memory")

// ===========================================================================
// Fused setup kernel: mask detect + msa->fp16 + both weight transposes (fp16)
// ===========================================================================
#define CONV_BLOCKS 8192
#define TRA_BLOCKS  192
#define TRB_BLOCKS  64

__device__ __forceinline__ void do_transpose(
    const float* __restrict__ W, __half* __restrict__ th,
    int K, int Nn, int n0, int k0, int t) {
    __shared__ float tsm[32][33];
    const int tx = t & 31, ty = t >> 5;
#pragma unroll
    for (int i = 0; i < 32; i += 8)
        tsm[ty + i][tx] = W[(size_t)(k0 + ty + i) * Nn + n0 + tx];
    __syncthreads();
#pragma unroll
    for (int i = 0; i < 32; i += 8)
        th[(size_t)(n0 + ty + i) * K + k0 + tx] = __float2half(tsm[tx][ty + i]);
}

__global__ __launch_bounds__(256)
void setup_kernel(const float* __restrict__ msa, const float* __restrict__ w_qkv,
                  const float* __restrict__ w_out, const unsigned char* __restrict__ mb,
                  __half* __restrict__ msa_h,
                  __half* __restrict__ wq_t, __half* __restrict__ wo_t) {
    const int b = blockIdx.x;
    const int t = threadIdx.x;
    if (b == 0) {
        int any = 0;
        for (int j = t; j < 4096; j += 256)
            any |= mb[j * 4 + 1] | mb[j * 4 + 2] | mb[j * 4 + 3];
        any = __syncthreads_or(any);
        if (t == 0) g_mask_is_byte = any ? 1 : 0;
    } else if (b <= CONV_BLOCKS) {
        const int i = (b - 1) * 256 + t;
        float4 v = ((const float4*)msa)[i];
        uint2 p;
        p.x = pack_h2(__float2half(v.x), __float2half(v.y));
        p.y = pack_h2(__float2half(v.z), __float2half(v.w));
        ((uint2*)msa_h)[i] = p;
    } else if (b <= CONV_BLOCKS + TRA_BLOCKS) {
        const int bb = b - 1 - CONV_BLOCKS;
        do_transpose(w_qkv, wq_t, 256, 768, (bb % 24) * 32, (bb / 24) * 32, t);
    } else {
        const int bb = b - 1 - CONV_BLOCKS - TRA_BLOCKS;
        do_transpose(w_out, wo_t, 256, 256, (bb % 8) * 32, (bb / 8) * 32, t);
    }
}

// ===========================================================================
// fp16 single-pass GEMM, cp.async 2-stage pipeline, BK=64. C = A @ Bt^T.
// ===========================================================================
#define GKSTR 72      // 64 + 8 pad (fp16 elems/row)
#define GARR  18432   // bytes per array: 128 * GKSTR * 2
#define GSTG  36864   // bytes per stage: 2 arrays

__global__ __launch_bounds__(256, 2)
void gemm_mma_pipe(const __half* __restrict__ Ag, const __half* __restrict__ Bg,
                   const float* __restrict__ bias, float* __restrict__ Cf,
                   __half* __restrict__ Ch, __half* __restrict__ Cl,
                   int M, int Nn, int K, int qcols) {
    extern __shared__ char smb[];
    const uint32_t sbase = smem_u32(smb);

    const int tid  = threadIdx.x;
    const int wid  = tid >> 5;
    const int lane = tid & 31;
    const int warp_m = wid & 3;
    const int warp_n = wid >> 2;

    const int m0 = blockIdx.y * 128;
    const int n0 = blockIdx.x * 128;

    float acc[2][8][4];
#pragma unroll
    for (int mt = 0; mt < 2; mt++)
#pragma unroll
        for (int nt = 0; nt < 8; nt++)
#pragma unroll
            for (int j = 0; j < 4; j++) acc[mt][nt][j] = 0.f;

    const int sr = tid >> 3;
    const int sc = (tid & 7) * 8;
#define STAGE_CHUNK(S, KC) do { \
        const uint32_t st = sbase + (S) * GSTG; \
        _Pragma("unroll") \
        for (int i = 0; i < 4; i++) { \
            const int r = sr + i * 32; \
            const uint32_t doff = (uint32_t)(r * GKSTR + sc) * 2; \
            cp16(st + doff,        Ag + (size_t)(m0 + r) * K + (KC) + sc); \
            cp16(st + GARR + doff, Bg + (size_t)(n0 + r) * K + (KC) + sc); \
        } \
    } while (0)

    STAGE_CHUNK(0, 0);
    CP_COMMIT();

    const int nchunk = K / 64;
    for (int kci = 0; kci < nchunk; kci++) {
        const int s = kci & 1;
        if (kci + 1 < nchunk) {
            STAGE_CHUNK(s ^ 1, (kci + 1) * 64);
            CP_COMMIT();
            CP_WAIT1();
        } else {
            CP_WAIT0();
        }
        __syncthreads();

        const uint32_t st = sbase + s * GSTG;
        const uint32_t aA = st        + (uint32_t)(warp_m * 32 * GKSTR) * 2;
        const uint32_t aB = st + GARR + (uint32_t)(warp_n * 64 * GKSTR) * 2;
        const int grp = lane >> 3;

#pragma unroll
        for (int ks = 0; ks < 64; ks += 16) {
            uint32_t ah[2][4];
            const uint32_t aoff = (uint32_t)((lane & 15) * GKSTR + ks + (lane >> 4) * 8) * 2;
            ldsm_x4(ah[0], aA + aoff);
            ldsm_x4(ah[1], aA + (uint32_t)(16 * GKSTR) * 2 + aoff);

            const uint32_t boff =
                (uint32_t)((((grp & 2) * 4) + (lane & 7)) * GKSTR + ks + (grp & 1) * 8) * 2;

            uint32_t b[4][4];
#pragma unroll
            for (int p = 0; p < 4; p++) ldsm_x4(b[p], aB + (uint32_t)(p * 16 * GKSTR) * 2 + boff);
#pragma unroll
            for (int mt = 0; mt < 2; mt++)
#pragma unroll
                for (int p = 0; p < 4; p++) {
                    mma_f16(acc[mt][2 * p],     ah[mt], &b[p][0]);
                    mma_f16(acc[mt][2 * p + 1], ah[mt], &b[p][2]);
                }
        }
        __syncthreads();
    }

    // Epilogue
    const int g  = lane >> 2;
    const int c2 = (lane & 3) * 2;
    const int mb = m0 + warp_m * 32;
    const int nb = n0 + warp_n * 64;
    if (Cf) {
#pragma unroll
        for (int mt = 0; mt < 2; mt++) {
#pragma unroll
            for (int nt = 0; nt < 8; nt++) {
                const int col = nb + nt * 8 + c2;
                float b0 = 0.f, b1 = 0.f;
                if (bias) { b0 = __ldg(bias + col); b1 = __ldg(bias + col + 1); }
                const int r0 = mb + mt * 16 + g;
                float2 v0 = { acc[mt][nt][0] + b0, acc[mt][nt][1] + b1 };
                float2 v1 = { acc[mt][nt][2] + b0, acc[mt][nt][3] + b1 };
                *(float2*)(Cf + (size_t)r0 * Nn + col)       = v0;
                *(float2*)(Cf + (size_t)(r0 + 8) * Nn + col) = v1;
            }
        }
    } else {
#pragma unroll
        for (int mt = 0; mt < 2; mt++) {
#pragma unroll
            for (int nt = 0; nt < 8; nt++) {
                const int col = nb + nt * 8 + c2;
                const bool isq = (col < qcols);
                const bool isk = (col >= qcols) && (col < 2 * qcols);
                const float sc0 = isq ? (QSCALE * LOG2E) : 1.f;
                const int r0 = mb + mt * 16 + g;
#pragma unroll
                for (int half = 0; half < 2; half++) {
                    float x = acc[mt][nt][2 * half]     * sc0;
                    float y = acc[mt][nt][2 * half + 1] * sc0;
                    __half hx = __float2half(x), hy = __float2half(y);
                    size_t o = (size_t)(r0 + half * 8) * Nn + col;
                    *(uint32_t*)(Ch + o) = pack_h2(hx, hy);
                    if (isk) {
                        *(uint32_t*)(Cl + o) =
                            pack_h2(__float2half(x - __half2float(hx)),
                                    __float2half(y - __half2float(hy)));
                    }
                }
            }
        }
    }
}

// ===========================================================================
// Pair bias (log2 domain): out = (pair@w_pb + b_pb)*log2e - 2*log2e
// ===========================================================================
__global__ __launch_bounds__(256)
void pair_bias_kernel(const float* __restrict__ pair, const float* __restrict__ w_pb,
                      const float* __restrict__ b_pb, float* __restrict__ bias_out) {
    __shared__ float sp[32][128];
    __shared__ float sw[128][8];
    __shared__ float sb[8];

    const int t = threadIdx.x;
    const int base = blockIdx.x * 32;

    for (int i = t; i < 32 * 128; i += 256)
        sp[i >> 7][i & 127] = pair[(size_t)(base + (i >> 7)) * 128 + (i & 127)];
    for (int i = t; i < 128 * 8; i += 256)
        sw[i >> 3][i & 7] = w_pb[i];
    if (t < 8) sb[t] = b_pb[t];
    __syncthreads();

    const int pi = t >> 3;
    const int h  = t & 7;
    float s = sb[h];
#pragma unroll 8
    for (int p = 0; p < 128; p++) s += sp[pi][p] * sw[p][h];
    bias_out[(size_t)h * (LL * LL) + base + pi] = s * LOG2E - 2.f * LOG2E;
}

// ===========================================================================
// Tensor-core attention with KEY COMPACTION (mask ~50% -> ~0.6x work, exact).
// Valid keys gathered into compacted smem; k-loop runs ceil(nvalid/64) chunks.
// S: 2-pass (q*(Kh+Kl)); PV: single-pass. Bias gathered via perm[].
// ===========================================================================
#define AKSTR 40

__global__ __launch_bounds__(256, 2)
void attn_mma_kernel(const __half* __restrict__ qb_hi,
                     const __half* __restrict__ qb_lo,
                     const float* __restrict__ bias,
                     const unsigned char* __restrict__ mask_raw,
                     __half* __restrict__ out_h) {
    extern __shared__ __half smba[];
    __half* Kh = smba;                    // 256 x AKSTR (compacted keys)
    __half* Kl = smba + 256 * AKSTR;
    __half* Vh = smba + 2 * 256 * AKSTR;
    __shared__ int      perm[256];        // compacted -> original key index
    __shared__ uint32_t cmask2[128];      // compacted-space validity (fp16 pairs)
    __shared__ int      s_nvalid;

    const int h   = blockIdx.x;
    const int n   = blockIdx.y;
    const int tid = threadIdx.x;
    const int wid = tid >> 5;
    const int lane = tid & 31;
    const int g   = lane >> 2;
    const int c2  = (lane & 3) * 2;

    // ---- 1) mask -> perm (warp 0, ballot prefix-sum; deterministic) ----
    if (wid == 0) {
        int base = 0;
        const int misb = g_mask_is_byte;
#pragma unroll
        for (int chunk = 0; chunk < 8; chunk++) {
            const int idx = chunk * 32 + lane;
            int m;
            if (misb) m = mask_raw[n * 256 + idx] != 0;
            else      m = ((const int*)mask_raw)[n * 256 + idx] != 0;
            const uint32_t bits = __ballot_sync(0xFFFFFFFF, m);
            if (m) perm[base + __popc(bits & ((1u << lane) - 1u))] = idx;
            base += __popc(bits);
        }
        if (lane == 0) s_nvalid = base;
    }
    __syncthreads();
    const int nvalid = s_nvalid;

    // ---- 2) pad perm (clamp to a valid row; keeps S finite) + cmask ----
    if (tid >= nvalid) perm[tid] = perm[nvalid > 0 ? nvalid - 1 : 0];
    if (tid < 128)
        cmask2[tid] = pack_h2(__float2half(2 * tid < nvalid ? 1.f : 0.f),
                              __float2half(2 * tid + 1 < nvalid ? 1.f : 0.f));
    __syncthreads();

    // ---- 3) gather-stage compacted K/V ----
    const size_t nb = (size_t)n * LL * 768;
    const __half* kh_src = qb_hi + nb + 256 + h * 32;
    const __half* kl_src = qb_lo + nb + 256 + h * 32;
    const __half* vh_src = qb_hi + nb + 512 + h * 32;

    const uint32_t aKh = smem_u32(Kh);
    const uint32_t aKl = smem_u32(Kl);
    const uint32_t aVh = smem_u32(Vh);
    {
        const int rb = tid >> 2, cc = (tid & 3) * 8;
#pragma unroll
        for (int i = 0; i < 4; i++) {
            const int r = rb + i * 64;
            const size_t go = (size_t)perm[r] * 768 + cc;
            const uint32_t doff = (uint32_t)(r * AKSTR + cc) * 2;
            cp16(aKh + doff, kh_src + go);
            cp16(aKl + doff, kl_src + go);
            cp16(aVh + doff, vh_src + go);
        }
        CP_COMMIT();
    }

    // ---- 4) Q fragments (single fp16, pre-scaled by QSCALE*LOG2E) ----
    uint32_t qf[2][2][4];
    const __half* qh_src = qb_hi + nb + h * 32;
#pragma unroll
    for (int mt = 0; mt < 2; mt++) {
        const int r0 = wid * 32 + mt * 16 + g;
#pragma unroll
        for (int ks2 = 0; ks2 < 2; ks2++) {
#pragma unroll
            for (int j = 0; j < 4; j++) {
                const int rr = r0 + (j & 1) * 8;
                const int kk = ks2 * 16 + (j >> 1) * 8 + c2;
                qf[mt][ks2][j] = *(const uint32_t*)(qh_src + (size_t)rr * 768 + kk);
            }
        }
    }
    CP_WAIT0();
    __syncthreads();

    const int grp = lane >> 3;
    const uint32_t ONES2 = 0x3C003C00u;
    uint32_t b_ones[2] = { ONES2, ONES2 };

    float oacc[2][4][4];
    float lacc[2][4];
#pragma unroll
    for (int mt = 0; mt < 2; mt++) {
#pragma unroll
        for (int nt = 0; nt < 4; nt++)
#pragma unroll
            for (int j = 0; j < 4; j++) oacc[mt][nt][j] = 0.f;
#pragma unroll
        for (int j = 0; j < 4; j++) lacc[mt][j] = 0.f;
    }

    const float* bh_base = bias + (size_t)h * (LL * LL);
    const int nchunk = (nvalid + 63) >> 6;

    for (int ci = 0; ci < nchunk; ci++) {
        const int kbase = ci * 64;
#pragma unroll
        for (int mt = 0; mt < 2; mt++) {
            float sacc[8][4];
#pragma unroll
            for (int nt = 0; nt < 8; nt++)
#pragma unroll
                for (int j = 0; j < 4; j++) sacc[nt][j] = 0.f;

            // ---- S = Q K^T (2-pass: q*(Kh+Kl)) over compacted keys ----
#pragma unroll
            for (int ks2 = 0; ks2 < 2; ks2++) {
                const uint32_t boff =
                    (uint32_t)(((grp & 2) * 4 + (lane & 7)) * AKSTR + ks2 * 16 + (grp & 1) * 8) * 2;
                uint32_t bh[4][4], bl[4][4];
#pragma unroll
                for (int p = 0; p < 4; p++) {
                    const uint32_t rofs = (uint32_t)((kbase + p * 16) * AKSTR) * 2;
                    ldsm_x4(bh[p], aKh + rofs + boff);
                    ldsm_x4(bl[p], aKl + rofs + boff);
                }
#pragma unroll
                for (int p = 0; p < 4; p++) {
                    mma_f16(sacc[2 * p],     qf[mt][ks2], &bh[p][0]);
                    mma_f16(sacc[2 * p + 1], qf[mt][ks2], &bh[p][2]);
                    mma_f16(sacc[2 * p],     qf[mt][ks2], &bl[p][0]);
                    mma_f16(sacc[2 * p + 1], qf[mt][ks2], &bl[p][2]);
                }
            }

            // ---- P = ex2(S + bias[q][perm[ci]]) * validity ----
            const int r0 = wid * 32 + mt * 16 + g;
            const float* bb = bh_base + (size_t)r0 * 256;
            uint32_t pa[4][4];
#pragma unroll
            for (int nt = 0; nt < 8; nt++) {
                const int col = kbase + nt * 8 + c2;
                const int k0 = perm[col];
                const int k1 = perm[col + 1];
                const float b00 = __ldg(bb + k0);
                const float b01 = __ldg(bb + k1);
                const float b10 = __ldg(bb + 8 * 256 + k0);
                const float b11 = __ldg(bb + 8 * 256 + k1);
                const uint32_t mk = cmask2[col >> 1];
                uint32_t e0 = ex2_h2(cvt_h2(sacc[nt][0] + b00, sacc[nt][1] + b01));
                uint32_t e1 = ex2_h2(cvt_h2(sacc[nt][2] + b10, sacc[nt][3] + b11));
                const int j = nt >> 1, q = (nt & 1) * 2;
                pa[j][q]     = mul_h2(e0, mk);
                pa[j][q + 1] = mul_h2(e1, mk);
            }

            // ---- row sums via ones-mma ----
#pragma unroll
            for (int j = 0; j < 4; j++)
                mma_f16(lacc[mt], pa[j], b_ones);

            // ---- O += P V (single-pass), V via ldmatrix.trans ----
#pragma unroll
            for (int j = 0; j < 4; j++) {
                const int krow = kbase + j * 16 + (grp & 1) * 8 + (lane & 7);
                uint32_t vb[2][4];
#pragma unroll
                for (int dp = 0; dp < 2; dp++) {
                    const uint32_t voff =
                        (uint32_t)(krow * AKSTR + dp * 16 + (grp >> 1) * 8) * 2;
                    ldsm_x4t(vb[dp], aVh + voff);
                }
#pragma unroll
                for (int dp = 0; dp < 2; dp++) {
                    mma_f16(oacc[mt][2 * dp],     pa[j], &vb[dp][0]);
                    mma_f16(oacc[mt][2 * dp + 1], pa[j], &vb[dp][2]);
                }
            }
        }
    }

    // normalize + store
#pragma unroll
    for (int mt = 0; mt < 2; mt++) {
        const float i0 = 1.f / lacc[mt][0];
        const float i1 = 1.f / lacc[mt][2];
        const int r0 = n * LL + wid * 32 + mt * 16 + g;
#pragma unroll
        for (int nt = 0; nt < 4; nt++) {
            const int col = h * 32 + nt * 8 + c2;
            *(uint32_t*)(out_h + (size_t)r0 * DD + col) =
                pack_h2(__float2half(oacc[mt][nt][0] * i0),
                        __float2half(oacc[mt][nt][1] * i0));
            *(uint32_t*)(out_h + (size_t)(r0 + 8) * DD + col) =
                pack_h2(__float2half(oacc[mt][nt][2] * i1),
                        __float2half(oacc[mt][nt][3] * i1));
        }
    }
}

// ===========================================================================
// Launch:  setup(0), pair_bias(1), QKV(2), attn(3), outproj(4)
// ===========================================================================
extern "C" void kernel_launch(void* const* d_in, const int* in_sizes, int n_in,
                              void* d_out, int out_size) {
    const float*         msa   = (const float*)d_in[0];
    const float*         pair  = (const float*)d_in[1];
    const unsigned char* maskp = (const unsigned char*)d_in[2];
    const float*         w_qkv = (const float*)d_in[3];
    const float*         w_pb  = (const float*)d_in[4];
    const float*         b_pb  = (const float*)d_in[5];
    const float*         w_out = (const float*)d_in[6];
    const float*         b_out = (const float*)d_in[7];
    float*               out   = (float*)d_out;

    float* bias_p;  cudaGetSymbolAddress((void**)&bias_p,  g_bias);
    __half *qb_hi, *qb_lo, *msa_h, *att_h, *wq_t, *wo_t;
    cudaGetSymbolAddress((void**)&qb_hi, g_qkvb_hi);
    cudaGetSymbolAddress((void**)&qb_lo, g_qkvb_lo);
    cudaGetSymbolAddress((void**)&msa_h, g_msa_h);
    cudaGetSymbolAddress((void**)&att_h, g_att_h);
    cudaGetSymbolAddress((void**)&wq_t,  g_wqkv_t);
    cudaGetSymbolAddress((void**)&wo_t,  g_wout_t);

    const int gemm_smem = 2 * GSTG;                  // 73728 B
    const int attn_smem = 3 * 256 * AKSTR * 2;       // 61440 B
    cudaFuncSetAttribute(gemm_mma_pipe,   cudaFuncAttributeMaxDynamicSharedMemorySize, gemm_smem);
    cudaFuncSetAttribute(attn_mma_kernel, cudaFuncAttributeMaxDynamicSharedMemorySize, attn_smem);

    // 0) fused setup
    setup_kernel<<<1 + CONV_BLOCKS + TRA_BLOCKS + TRB_BLOCKS, 256>>>(
        msa, w_qkv, w_out, maskp, msa_h, wq_t, wo_t);

    // 1) Pair bias (log2 domain)
    pair_bias_kernel<<<(LL * LL) / 32, 256>>>(pair, w_pb, b_pb, bias_p);

    // 2) QKV projection -> fp16 hi (+lo for k cols), q pre-scaled
    {
        dim3 grid(768 / 128, (NN * LL) / 128);
        gemm_mma_pipe<<<grid, 256, gemm_smem>>>(msa_h, wq_t,
                                                nullptr, nullptr, qb_hi, qb_lo,
                                                NN * LL, 768, DD, 256);
    }

    // 3) Tensor-core attention per (h, n), key-compacted  [profiled slot]
    {
        dim3 grid(HH, NN);
        attn_mma_kernel<<<grid, 256, attn_smem>>>(qb_hi, qb_lo, bias_p, maskp, att_h);
    }

    // 4) Output projection: fp32 out + b_out
    {
        dim3 grid(DD / 128, (NN * LL) / 128);
        gemm_mma_pipe<<<grid, 256, gemm_smem>>>(att_h, wo_t,
                                                b_out, out, nullptr, nullptr,
                                                NN * LL, DD, DD, 0);
    }
}